// round 1
// baseline (speedup 1.0000x reference)
#include <cuda_runtime.h>
#include <cstdint>
#include <cstddef>

#define T_LEN 512
#define BATCH 64
#define ISZ   256
#define HID   512
#define NCOL  2048      // 4*HID
#define GRID2 128       // persistent blocks, 1/SM, all co-resident (<=148 SMs)

// ---------------- device scratch (no runtime allocation allowed) ----------------
__device__ float g_gx[(size_t)T_LEN * NCOL * BATCH];   // [T][2048][64], bx+bh folded in
__device__ float g_h[2][BATCH * HID];                  // h double buffer
__device__ unsigned g_bar_count;
__device__ volatile unsigned g_bar_gen;

// ---------------- packed fp32x2 FMA (2x fp32 rate on sm_103a) ----------------
__device__ __forceinline__ unsigned long long fma2(unsigned long long a,
                                                   unsigned long long b,
                                                   unsigned long long c) {
    unsigned long long d;
    asm("fma.rn.f32x2 %0, %1, %2, %3;" : "=l"(d) : "l"(a), "l"(b), "l"(c));
    return d;
}
__device__ __forceinline__ float hsum2(unsigned long long v) {
    float lo, hi;
    asm("mov.b64 {%0,%1}, %2;" : "=f"(lo), "=f"(hi) : "l"(v));
    return lo + hi;
}

__device__ __forceinline__ float sigf(float x) {
    return 1.0f / (1.0f + __expf(-x));
}
__device__ __forceinline__ float tanh_acc(float x) {
    float ax = fabsf(x);
    float e  = __expf(-2.0f * ax);
    float r  = (1.0f - e) / (1.0f + e);
    return copysignf(r, x);
}

// =====================================================================
// Phase 1: gx[t][n][b] = dot(x[t,b,:], Wx[n,:]) + bx[n] + bh[n]
//   grid (32, 512): block covers one t and 64 columns n, all 64 b.
// =====================================================================
#define P1_PAD 132

extern "C" __global__ void __launch_bounds__(256, 2)
lstm_phase1(const float* __restrict__ x, const float* __restrict__ Wx,
            const float* __restrict__ bx, const float* __restrict__ bh)
{
    extern __shared__ float smem[];
    float* xs   = smem;                 // [64][132]
    float* ws   = smem + 64 * P1_PAD;   // [64][132]
    float* sbuf = smem;                 // alias xs after compute: [64][68]

    const int t   = blockIdx.y;
    const int n0  = blockIdx.x * 64;
    const int tid = threadIdx.x;
    const int nq  = tid & 15;
    const int bq  = tid >> 4;           // 0..15

    unsigned long long acc[4][4];       // [rb][rn]
    #pragma unroll
    for (int a = 0; a < 4; a++)
        #pragma unroll
        for (int c = 0; c < 4; c++) acc[a][c] = 0ull;

    #pragma unroll
    for (int ks = 0; ks < 2; ks++) {
        const int k0 = ks * 128;
        __syncthreads();
        // stage x[t][b][k0..k0+128) -> xs
        for (int e = tid; e < 64 * 32; e += 256) {
            int bb = e >> 5, kq = e & 31;
            float4 v = *reinterpret_cast<const float4*>(
                &x[((size_t)t * BATCH + bb) * ISZ + k0 + kq * 4]);
            *reinterpret_cast<float4*>(&xs[bb * P1_PAD + kq * 4]) = v;
        }
        // stage Wx[n0+r][k0..k0+128) -> ws
        for (int e = tid; e < 64 * 32; e += 256) {
            int r = e >> 5, kq = e & 31;
            float4 v = *reinterpret_cast<const float4*>(
                &Wx[(size_t)(n0 + r) * ISZ + k0 + kq * 4]);
            *reinterpret_cast<float4*>(&ws[r * P1_PAD + kq * 4]) = v;
        }
        __syncthreads();

        #pragma unroll 4
        for (int k4 = 0; k4 < 128; k4 += 4) {
            ulonglong2 xv[4], wv[4];
            #pragma unroll
            for (int rb = 0; rb < 4; rb++)
                xv[rb] = *reinterpret_cast<const ulonglong2*>(
                    &xs[(bq + 16 * rb) * P1_PAD + k4]);
            #pragma unroll
            for (int rn = 0; rn < 4; rn++)
                wv[rn] = *reinterpret_cast<const ulonglong2*>(
                    &ws[(nq + 16 * rn) * P1_PAD + k4]);
            #pragma unroll
            for (int rb = 0; rb < 4; rb++)
                #pragma unroll
                for (int rn = 0; rn < 4; rn++) {
                    acc[rb][rn] = fma2(xv[rb].x, wv[rn].x, acc[rb][rn]);
                    acc[rb][rn] = fma2(xv[rb].y, wv[rn].y, acc[rb][rn]);
                }
        }
    }
    __syncthreads();

    // transpose through shared for coalesced [n][b] stores
    #pragma unroll
    for (int rb = 0; rb < 4; rb++)
        #pragma unroll
        for (int rn = 0; rn < 4; rn++)
            sbuf[(nq + 16 * rn) * 68 + (bq + 16 * rb)] = hsum2(acc[rb][rn]);
    __syncthreads();

    for (int e = tid; e < 64 * 16; e += 256) {
        int row = e >> 4, c4 = e & 15;
        int n = n0 + row;
        float bias = bx[n] + bh[n];
        float4 v = *reinterpret_cast<float4*>(&sbuf[row * 68 + c4 * 4]);
        v.x += bias; v.y += bias; v.z += bias; v.w += bias;
        *reinterpret_cast<float4*>(
            &g_gx[((size_t)t * NCOL + n) * BATCH + c4 * 4]) = v;
    }
}

// =====================================================================
// Phase 2: persistent recurrence. 128 blocks x 256 threads.
//   block bid owns hidden units j in [bid*4, bid*4+4); thread = (b, jj).
// =====================================================================
#define HS_PAD 516
#define WS_PAD 520

__device__ __forceinline__ void copy_chunk_async(float* hs, const float* hsrc,
                                                 int ci, int tid) {
    const int kbase = ci * 128;
    #pragma unroll
    for (int r = 0; r < 8; r++) {
        int e  = tid + r * 256;       // 0..2047 -> 2048 x 16B
        int bb = e >> 5, kq = e & 31;
        unsigned dst = (unsigned)__cvta_generic_to_shared(
            &hs[bb * HS_PAD + kbase + kq * 4]);
        const float* src = &hsrc[bb * HID + kbase + kq * 4];
        asm volatile("cp.async.cg.shared.global [%0], [%1], 16;"
                     :: "r"(dst), "l"(src) : "memory");
    }
}
__device__ __forceinline__ void cpa_commit() {
    asm volatile("cp.async.commit_group;" ::: "memory");
}
template <int N>
__device__ __forceinline__ void cpa_wait() {
    asm volatile("cp.async.wait_group %0;" :: "n"(N) : "memory");
}

__device__ __forceinline__ void grid_barrier(unsigned& local_gen) {
    __syncthreads();
    if (threadIdx.x == 0) {
        __threadfence();
        unsigned a = atomicAdd(&g_bar_count, 1u);
        if (a == GRID2 - 1) {
            atomicExch(&g_bar_count, 0u);
            __threadfence();
            g_bar_gen = local_gen + 1;
        } else {
            while (g_bar_gen != local_gen + 1) { __nanosleep(32); }
            __threadfence();
        }
    }
    local_gen += 1;
    __syncthreads();
}

extern "C" __global__ void __launch_bounds__(256, 1)
lstm_phase2(const float* __restrict__ Wh, float* __restrict__ out)
{
    extern __shared__ float smem[];
    float* hs = smem;                   // [64][516] h_prev
    float* ws = smem + 64 * HS_PAD;     // [16][520] Wh slice (4 gates x 4 units)

    const int tid = threadIdx.x;
    const int bid = blockIdx.x;
    const int b   = tid >> 2;           // 0..63
    const int jj  = tid & 3;            // 0..3
    const int j   = bid * 4 + jj;

    // Load this block's Wh slice once; resident for all 512 steps.
    for (int e = tid; e < 16 * 128; e += 256) {
        int row = e >> 7, kq = e & 127;
        int g = row >> 2, jx = row & 3;
        float4 v = *reinterpret_cast<const float4*>(
            &Wh[((size_t)(g * HID + bid * 4 + jx)) * HID + kq * 4]);
        *reinterpret_cast<float4*>(&ws[row * WS_PAD + kq * 4]) = v;
    }

    unsigned local_gen = g_bar_gen;     // persists across graph replays
    float c_state = 0.0f;

    for (int t = 0; t < T_LEN; t++) {
        const int rb = t & 1;
        const int wb = rb ^ 1;

        // prefetch gx early (independent of h)
        float gxv[4];
        #pragma unroll
        for (int g = 0; g < 4; g++)
            gxv[g] = g_gx[((size_t)t * NCOL + g * HID + j) * BATCH + b];

        unsigned long long acc[4] = {0ull, 0ull, 0ull, 0ull};

        if (t > 0) {
            const float* hsrc = g_h[rb];
            copy_chunk_async(hs, hsrc, 0, tid);
            cpa_commit();
            #pragma unroll
            for (int ci = 0; ci < 4; ci++) {
                if (ci < 3) {
                    copy_chunk_async(hs, hsrc, ci + 1, tid);
                    cpa_commit();
                    cpa_wait<1>();      // chunk ci landed
                } else {
                    cpa_wait<0>();
                }
                __syncthreads();
                const int kbase = ci * 128;
                #pragma unroll 4
                for (int k4 = 0; k4 < 128; k4 += 4) {
                    ulonglong2 h2 = *reinterpret_cast<const ulonglong2*>(
                        &hs[b * HS_PAD + kbase + k4]);
                    #pragma unroll
                    for (int g = 0; g < 4; g++) {
                        ulonglong2 w2 = *reinterpret_cast<const ulonglong2*>(
                            &ws[(g * 4 + jj) * WS_PAD + kbase + k4]);
                        acc[g] = fma2(h2.x, w2.x, acc[g]);
                        acc[g] = fma2(h2.y, w2.y, acc[g]);
                    }
                }
            }
        }

        float gate[4];
        #pragma unroll
        for (int g = 0; g < 4; g++) gate[g] = hsum2(acc[g]) + gxv[g];

        float f  = sigf(gate[0]);
        float i  = sigf(gate[1]);
        float o  = sigf(gate[2]);
        float cc = tanh_acc(gate[3]);
        c_state  = f * c_state + i * cc;
        float h  = o * tanh_acc(c_state);

        g_h[wb][b * HID + j] = h;
        out[((size_t)t * BATCH + b) * HID + j] = h;
        if (t == T_LEN - 1) {
            out[(size_t)T_LEN * BATCH * HID + (size_t)b * HID + j] = h;       // h_last
            out[(size_t)T_LEN * BATCH * HID + (size_t)BATCH * HID
                + (size_t)b * HID + j] = c_state;                             // c_last
        }
        grid_barrier(local_gen);
    }
}

// =====================================================================
// launch
// =====================================================================
extern "C" void kernel_launch(void* const* d_in, const int* in_sizes, int n_in,
                              void* d_out, int out_size) {
    (void)in_sizes; (void)n_in; (void)out_size;
    const float* x  = (const float*)d_in[0];
    const float* Wx = (const float*)d_in[1];
    const float* bx = (const float*)d_in[2];
    const float* Wh = (const float*)d_in[3];
    const float* bh = (const float*)d_in[4];
    float* out = (float*)d_out;

    const int smem1 = 2 * 64 * P1_PAD * sizeof(float);                 // 67584 B
    const int smem2 = (64 * HS_PAD + 16 * WS_PAD) * sizeof(float);     // 165376 B
    cudaFuncSetAttribute(lstm_phase1, cudaFuncAttributeMaxDynamicSharedMemorySize, smem1);
    cudaFuncSetAttribute(lstm_phase2, cudaFuncAttributeMaxDynamicSharedMemorySize, smem2);

    dim3 g1(32, T_LEN);
    lstm_phase1<<<g1, 256, smem1>>>(x, Wx, bx, bh);
    lstm_phase2<<<GRID2, 256, smem2>>>(Wh, out);
}

// round 2
// speedup vs baseline: 1.0135x; 1.0135x over previous
#include <cuda_runtime.h>
#include <cstdint>
#include <cstddef>

#define T_LEN 512
#define BATCH 64
#define ISZ   256
#define HID   512
#define NCOL  2048      // 4*HID
#define GRID2 128       // persistent blocks, 1/SM, all co-resident

// ---------------- device scratch ----------------
__device__ float g_gx[(size_t)T_LEN * NCOL * BATCH];   // [T][2048][64], bx+bh folded in
__device__ float g_h[2][BATCH * HID];                  // h double buffer
__device__ unsigned g_bar_count;
__device__ unsigned g_bar_gen;

// ---------------- packed fp32x2 FMA ----------------
__device__ __forceinline__ unsigned long long fma2(unsigned long long a,
                                                   unsigned long long b,
                                                   unsigned long long c) {
    unsigned long long d;
    asm("fma.rn.f32x2 %0, %1, %2, %3;" : "=l"(d) : "l"(a), "l"(b), "l"(c));
    return d;
}
__device__ __forceinline__ float hsum2(unsigned long long v) {
    float lo, hi;
    asm("mov.b64 {%0,%1}, %2;" : "=f"(lo), "=f"(hi) : "l"(v));
    return lo + hi;
}
__device__ __forceinline__ float sigf(float x) {
    return 1.0f / (1.0f + __expf(-x));
}
__device__ __forceinline__ float tanh_acc(float x) {
    float ax = fabsf(x);
    float e  = __expf(-2.0f * ax);
    float r  = (1.0f - e) / (1.0f + e);
    return copysignf(r, x);
}

// =====================================================================
// Phase 1 (unchanged, known-correct): gx[t][n][b] = x[t,b,:]·Wx[n,:] + bx[n]+bh[n]
// =====================================================================
#define P1_PAD 132

extern "C" __global__ void __launch_bounds__(256, 2)
lstm_phase1(const float* __restrict__ x, const float* __restrict__ Wx,
            const float* __restrict__ bx, const float* __restrict__ bh)
{
    extern __shared__ float smem[];
    float* xs   = smem;
    float* ws   = smem + 64 * P1_PAD;
    float* sbuf = smem;

    const int t   = blockIdx.y;
    const int n0  = blockIdx.x * 64;
    const int tid = threadIdx.x;
    const int nq  = tid & 15;
    const int bq  = tid >> 4;

    unsigned long long acc[4][4];
    #pragma unroll
    for (int a = 0; a < 4; a++)
        #pragma unroll
        for (int c = 0; c < 4; c++) acc[a][c] = 0ull;

    #pragma unroll
    for (int ks = 0; ks < 2; ks++) {
        const int k0 = ks * 128;
        __syncthreads();
        for (int e = tid; e < 64 * 32; e += 256) {
            int bb = e >> 5, kq = e & 31;
            float4 v = *reinterpret_cast<const float4*>(
                &x[((size_t)t * BATCH + bb) * ISZ + k0 + kq * 4]);
            *reinterpret_cast<float4*>(&xs[bb * P1_PAD + kq * 4]) = v;
        }
        for (int e = tid; e < 64 * 32; e += 256) {
            int r = e >> 5, kq = e & 31;
            float4 v = *reinterpret_cast<const float4*>(
                &Wx[(size_t)(n0 + r) * ISZ + k0 + kq * 4]);
            *reinterpret_cast<float4*>(&ws[r * P1_PAD + kq * 4]) = v;
        }
        __syncthreads();

        #pragma unroll 4
        for (int k4 = 0; k4 < 128; k4 += 4) {
            ulonglong2 xv[4], wv[4];
            #pragma unroll
            for (int rb = 0; rb < 4; rb++)
                xv[rb] = *reinterpret_cast<const ulonglong2*>(
                    &xs[(bq + 16 * rb) * P1_PAD + k4]);
            #pragma unroll
            for (int rn = 0; rn < 4; rn++)
                wv[rn] = *reinterpret_cast<const ulonglong2*>(
                    &ws[(nq + 16 * rn) * P1_PAD + k4]);
            #pragma unroll
            for (int rb = 0; rb < 4; rb++)
                #pragma unroll
                for (int rn = 0; rn < 4; rn++) {
                    acc[rb][rn] = fma2(xv[rb].x, wv[rn].x, acc[rb][rn]);
                    acc[rb][rn] = fma2(xv[rb].y, wv[rn].y, acc[rb][rn]);
                }
        }
    }
    __syncthreads();

    #pragma unroll
    for (int rb = 0; rb < 4; rb++)
        #pragma unroll
        for (int rn = 0; rn < 4; rn++)
            sbuf[(nq + 16 * rn) * 68 + (bq + 16 * rb)] = hsum2(acc[rb][rn]);
    __syncthreads();

    for (int e = tid; e < 64 * 16; e += 256) {
        int row = e >> 4, c4 = e & 15;
        int n = n0 + row;
        float bias = bx[n] + bh[n];
        float4 v = *reinterpret_cast<float4*>(&sbuf[row * 68 + c4 * 4]);
        v.x += bias; v.y += bias; v.z += bias; v.w += bias;
        *reinterpret_cast<float4*>(
            &g_gx[((size_t)t * NCOL + n) * BATCH + c4 * 4]) = v;
    }
}

// =====================================================================
// Phase 2: persistent recurrence, 128 blocks x 512 threads.
//   thread = (kh, b, jj): kh = k-half, block owns units j in [bid*4, bid*4+4)
//   warp = 8 b x 4 jj (one kh): w-loads broadcast over b, h-loads 8 distinct.
//   Each warp stages its OWN hs slice (8 b x its k-half) via cp.async, so
//   per-warp wait_group is sufficient — no mid-step __syncthreads.
// =====================================================================
#define HS_PAD 516
#define WS_PAD 520
#define NTHR2  512

__device__ __forceinline__ void cpa_commit() {
    asm volatile("cp.async.commit_group;" ::: "memory");
}
template <int N>
__device__ __forceinline__ void cpa_wait() {
    asm volatile("cp.async.wait_group %0;" :: "n"(N) : "memory");
}

// copy 8 rows [b0..b0+8) x 128 floats at kofs, by one warp (lane = lane id)
__device__ __forceinline__ void warp_copy_chunk(float* hs, const float* hsrc,
                                                int b0, int kofs, int lane) {
    #pragma unroll
    for (int p = lane; p < 256; p += 32) {
        int r  = p >> 5;          // 0..7
        int kq = p & 31;          // 0..31 (x4 floats = 16B)
        unsigned dst = (unsigned)__cvta_generic_to_shared(
            &hs[(b0 + r) * HS_PAD + kofs + kq * 4]);
        const float* src = &hsrc[(size_t)(b0 + r) * HID + kofs + kq * 4];
        asm volatile("cp.async.cg.shared.global [%0], [%1], 16;"
                     :: "r"(dst), "l"(src) : "memory");
    }
}

// accumulate 128-k chunk into 8 independent chains
__device__ __forceinline__ void dot_chunk(const float* __restrict__ hrow,
                                          const float* __restrict__ ws,
                                          int jj, int kofs,
                                          unsigned long long accx[4],
                                          unsigned long long accy[4]) {
    #pragma unroll 4
    for (int k4 = 0; k4 < 128; k4 += 4) {
        ulonglong2 h2 = *reinterpret_cast<const ulonglong2*>(&hrow[kofs + k4]);
        #pragma unroll
        for (int g = 0; g < 4; g++) {
            ulonglong2 w2 = *reinterpret_cast<const ulonglong2*>(
                &ws[(g * 4 + jj) * WS_PAD + kofs + k4]);
            accx[g] = fma2(h2.x, w2.x, accx[g]);
            accy[g] = fma2(h2.y, w2.y, accy[g]);
        }
    }
}

extern "C" __global__ void __launch_bounds__(NTHR2, 1)
lstm_phase2(const float* __restrict__ Wh, float* __restrict__ out)
{
    extern __shared__ float smem[];
    float* hs  = smem;                          // [64][516]
    float* ws  = smem + 64 * HS_PAD;            // [16][520]
    float* red = smem + 64 * HS_PAD + 16 * WS_PAD;  // [256][4]

    const int tid  = threadIdx.x;
    const int bid  = blockIdx.x;
    const int lane = tid & 31;
    const int kh   = tid >> 8;                  // 0/1: k-half
    const int t8   = tid & 255;
    const int b    = t8 >> 2;                   // 0..63
    const int jj   = t8 & 3;                    // 0..3
    const int j    = bid * 4 + jj;
    const int wb0  = ((tid >> 5) & 7) * 8;      // first b-row of this warp
    const int kA   = kh * 256;                  // warp's first chunk
    const int kB   = kA + 128;                  // warp's second chunk

    // Wh slice resident for all steps
    for (int e = tid; e < 16 * 128; e += NTHR2) {
        int row = e >> 7, kq = e & 127;
        int g = row >> 2, jx = row & 3;
        float4 v = *reinterpret_cast<const float4*>(
            &Wh[((size_t)(g * HID + bid * 4 + jx)) * HID + kq * 4]);
        *reinterpret_cast<float4*>(&ws[row * WS_PAD + kq * 4]) = v;
    }

    unsigned local_gen;
    asm volatile("ld.acquire.gpu.global.u32 %0, [%1];"
                 : "=r"(local_gen) : "l"(&g_bar_gen));
    float c_state = 0.0f;
    __syncthreads();   // ws ready

    for (int t = 0; t < T_LEN; t++) {
        const int rb = t & 1;
        const int wbuf = rb ^ 1;

        // prefetch gx (only finalizing half needs it)
        float gxv[4] = {0.f, 0.f, 0.f, 0.f};
        if (kh == 0) {
            #pragma unroll
            for (int g = 0; g < 4; g++)
                gxv[g] = g_gx[((size_t)t * NCOL + g * HID + j) * BATCH + b];
        }

        unsigned long long accx[4] = {0ull, 0ull, 0ull, 0ull};
        unsigned long long accy[4] = {0ull, 0ull, 0ull, 0ull};

        if (t > 0) {
            const float* hsrc = g_h[rb];
            warp_copy_chunk(hs, hsrc, wb0, kA, lane); cpa_commit();
            warp_copy_chunk(hs, hsrc, wb0, kB, lane); cpa_commit();
            const float* hrow = &hs[b * HS_PAD];
            cpa_wait<1>();
            dot_chunk(hrow, ws, jj, kA, accx, accy);
            cpa_wait<0>();
            dot_chunk(hrow, ws, jj, kB, accx, accy);
        }

        float part[4];
        #pragma unroll
        for (int g = 0; g < 4; g++) part[g] = hsum2(accx[g]) + hsum2(accy[g]);

        if (kh == 1) {
            float4 pv = make_float4(part[0], part[1], part[2], part[3]);
            *reinterpret_cast<float4*>(&red[t8 * 4]) = pv;
        }
        __syncthreads();   // partials ready; hs reads complete (safe to refill next step)

        if (kh == 0) {
            float4 pv = *reinterpret_cast<float4*>(&red[t8 * 4]);
            float gate0 = part[0] + pv.x + gxv[0];
            float gate1 = part[1] + pv.y + gxv[1];
            float gate2 = part[2] + pv.z + gxv[2];
            float gate3 = part[3] + pv.w + gxv[3];

            float f  = sigf(gate0);
            float i  = sigf(gate1);
            float o  = sigf(gate2);
            float cc = tanh_acc(gate3);
            c_state  = f * c_state + i * cc;
            float h  = o * tanh_acc(c_state);

            g_h[wbuf][b * HID + j] = h;
            out[((size_t)t * BATCH + b) * HID + j] = h;
            if (t == T_LEN - 1) {
                out[(size_t)T_LEN * BATCH * HID + (size_t)b * HID + j] = h;
                out[(size_t)T_LEN * BATCH * HID + (size_t)BATCH * HID
                    + (size_t)b * HID + j] = c_state;
            }
            __threadfence();   // make h stores visible before arrival
        }
        __syncthreads();

        // grid barrier: tid0 arrives, warp0 polls with acquire, block-wide sync
        const unsigned target = local_gen + 1;
        if (tid == 0) {
            unsigned a = atomicAdd(&g_bar_count, 1u);
            if (a == GRID2 - 1) {
                atomicExch(&g_bar_count, 0u);
                asm volatile("st.release.gpu.global.u32 [%0], %1;"
                             :: "l"(&g_bar_gen), "r"(target) : "memory");
            }
        }
        if (tid < 32) {
            unsigned v;
            do {
                asm volatile("ld.acquire.gpu.global.u32 %0, [%1];"
                             : "=r"(v) : "l"(&g_bar_gen));
                if (v != target) __nanosleep(20);
            } while (v != target);
        }
        local_gen = target;
        __syncthreads();
    }
}

// =====================================================================
// launch
// =====================================================================
extern "C" void kernel_launch(void* const* d_in, const int* in_sizes, int n_in,
                              void* d_out, int out_size) {
    (void)in_sizes; (void)n_in; (void)out_size;
    const float* x  = (const float*)d_in[0];
    const float* Wx = (const float*)d_in[1];
    const float* bx = (const float*)d_in[2];
    const float* Wh = (const float*)d_in[3];
    const float* bh = (const float*)d_in[4];
    float* out = (float*)d_out;

    const int smem1 = 2 * 64 * P1_PAD * sizeof(float);
    const int smem2 = (64 * HS_PAD + 16 * WS_PAD + 256 * 4) * sizeof(float);
    cudaFuncSetAttribute(lstm_phase1, cudaFuncAttributeMaxDynamicSharedMemorySize, smem1);
    cudaFuncSetAttribute(lstm_phase2, cudaFuncAttributeMaxDynamicSharedMemorySize, smem2);

    dim3 g1(32, T_LEN);
    lstm_phase1<<<g1, 256, smem1>>>(x, Wx, bx, bh);
    lstm_phase2<<<GRID2, NTHR2, smem2>>>(Wh, out);
}